// round 16
// baseline (speedup 1.0000x reference)
#include <cuda_runtime.h>

// Problem constants
#define PP      128                 // polygons
#define NN      128                 // pred points per polygon per level
#define MM      1024                // gt points per polygon
#define CHUNKS  8
#define CM      (MM/CHUNKS)         // 128 gt points per chunk
#define LVL_STRIDE (PP*NN)          // 16384

// level weights / (3 * P * N)
#define W0 (0.2f/49152.0f)
#define W1 (0.3f/49152.0f)
#define W2 (0.5f/49152.0f)

typedef unsigned long long u64;

// Scratch (no allocations allowed)
__device__ float g_partial[CHUNKS][3 * LVL_STRIDE];
__device__ float g_poly[PP];
__device__ int   g_cnt[PP];         // per-polygon tickets (zero-init; combiner resets)
__device__ int   g_cnt2;            // global ticket (zero-init; winner resets)

// ---- packed f32x2 helpers (sm_103a). fma2 is pure (non-volatile): schedulable. ----
__device__ __forceinline__ u64 pack2(float x) {
    u64 r; asm("mov.b64 %0, {%1, %1};" : "=l"(r) : "f"(x)); return r;
}
__device__ __forceinline__ u64 fma2(u64 a, u64 b, u64 c) {
    u64 d; asm("fma.rn.f32x2 %0, %1, %2, %3;" : "=l"(d) : "l"(a), "l"(b), "l"(c)); return d;
}
__device__ __forceinline__ void min2acc(float& m0, float& m1, u64 t) {
    float2 f = *reinterpret_cast<float2*>(&t);
    m0 = fminf(m0, f.x);
    m1 = fminf(m1, f.y);
}

// Single kernel: grid (CHUNKS, PP), 64 threads; 2 points x 3 levels per thread.
// Loop byte-identical to R6's k_partial. Tail fused via tid0-only fence+ticket
// (the grid_group::sync release pattern: bar.sync -> single-thread membar+atomic).
__global__ __launch_bounds__(64) void k_all(
    const float* __restrict__ pred0, const float* __restrict__ pred1,
    const float* __restrict__ pred2, const float* __restrict__ gt,
    float* __restrict__ out)
{
    __shared__ __align__(16) float sA[CM];
    __shared__ __align__(16) float sB[CM];
    __shared__ __align__(16) float sC[CM];
    __shared__ int s_ticket;
    __shared__ float s_w[2];

    const int ch  = blockIdx.x;
    const int p   = blockIdx.y;
    const int tid = threadIdx.x;

    // Load gt chunk, precompute A=-2gx, B=-2gy, C=|g|^2  (128 pts by 64 threads)
    {
        const float2* gsrc = (const float2*)(gt + ((size_t)p * MM + (size_t)ch * CM) * 2);
        #pragma unroll
        for (int k = 0; k < 2; k++) {
            int m = tid + k * 64;
            float2 g = gsrc[m];
            sA[m] = -2.0f * g.x;
            sB[m] = -2.0f * g.y;
            sC[m] = fmaf(g.x, g.x, g.y * g.y);
        }
    }

    // Two points per thread, 3 levels each; coords are [...,1:] of last dim 3
    const int n0 = 2 * tid, n1 = 2 * tid + 1;
    const int ba = (p * NN + n0) * 3;
    const int bb = (p * NN + n1) * 3;
    const float x0a = pred0[ba + 1], y0a = pred0[ba + 2];
    const float x1a = pred1[ba + 1], y1a = pred1[ba + 2];
    const float x2a = pred2[ba + 1], y2a = pred2[ba + 2];
    const float x0b = pred0[bb + 1], y0b = pred0[bb + 2];
    const float x1b = pred1[bb + 1], y1b = pred1[bb + 2];
    const float x2b = pred2[bb + 1], y2b = pred2[bb + 2];
    __syncthreads();

    const u64 X0a = pack2(x0a), Y0a = pack2(y0a), X0b = pack2(x0b), Y0b = pack2(y0b);
    const u64 X1a = pack2(x1a), Y1a = pack2(y1a), X1b = pack2(x1b), Y1b = pack2(y1b);
    const u64 X2a = pack2(x2a), Y2a = pack2(y2a), X2b = pack2(x2b), Y2b = pack2(y2b);

    const float INF = __int_as_float(0x7f800000);
    float m0a0 = INF, m0a1 = INF, m0b0 = INF, m0b1 = INF;
    float m1a0 = INF, m1a1 = INF, m1b0 = INF, m1b1 = INF;
    float m2a0 = INF, m2a1 = INF, m2b0 = INF, m2b1 = INF;

    const ulonglong2* A2 = (const ulonglong2*)sA;   // plain derefs -> schedulable LDS.128
    const ulonglong2* B2 = (const ulonglong2*)sB;
    const ulonglong2* C2 = (const ulonglong2*)sC;

    #pragma unroll 8
    for (int i = 0; i < CM / 4; i++) {              // 4 gt points per iteration
        ulonglong2 av = A2[i], bv = B2[i], cv = C2[i];
        // level 0
        min2acc(m0a0, m0a1, fma2(Y0a, bv.x, fma2(X0a, av.x, cv.x)));
        min2acc(m0a0, m0a1, fma2(Y0a, bv.y, fma2(X0a, av.y, cv.y)));
        min2acc(m0b0, m0b1, fma2(Y0b, bv.x, fma2(X0b, av.x, cv.x)));
        min2acc(m0b0, m0b1, fma2(Y0b, bv.y, fma2(X0b, av.y, cv.y)));
        // level 1
        min2acc(m1a0, m1a1, fma2(Y1a, bv.x, fma2(X1a, av.x, cv.x)));
        min2acc(m1a0, m1a1, fma2(Y1a, bv.y, fma2(X1a, av.y, cv.y)));
        min2acc(m1b0, m1b1, fma2(Y1b, bv.x, fma2(X1b, av.x, cv.x)));
        min2acc(m1b0, m1b1, fma2(Y1b, bv.y, fma2(X1b, av.y, cv.y)));
        // level 2
        min2acc(m2a0, m2a1, fma2(Y2a, bv.x, fma2(X2a, av.x, cv.x)));
        min2acc(m2a0, m2a1, fma2(Y2a, bv.y, fma2(X2a, av.y, cv.y)));
        min2acc(m2b0, m2b1, fma2(Y2b, bv.x, fma2(X2b, av.x, cv.x)));
        min2acc(m2b0, m2b1, fma2(Y2b, bv.y, fma2(X2b, av.y, cv.y)));
    }

    const int pta = p * NN + n0;
    const int ptb = p * NN + n1;
    g_partial[ch][0 * LVL_STRIDE + pta] = fminf(m0a0, m0a1) + fmaf(x0a, x0a, y0a * y0a);
    g_partial[ch][0 * LVL_STRIDE + ptb] = fminf(m0b0, m0b1) + fmaf(x0b, x0b, y0b * y0b);
    g_partial[ch][1 * LVL_STRIDE + pta] = fminf(m1a0, m1a1) + fmaf(x1a, x1a, y1a * y1a);
    g_partial[ch][1 * LVL_STRIDE + ptb] = fminf(m1b0, m1b1) + fmaf(x1b, x1b, y1b * y1b);
    g_partial[ch][2 * LVL_STRIDE + pta] = fminf(m2a0, m2a1) + fmaf(x2a, x2a, y2a * y2a);
    g_partial[ch][2 * LVL_STRIDE + ptb] = fminf(m2b0, m2b1) + fmaf(x2b, x2b, y2b * y2b);

    // ---- per-polygon ticket (grid.sync release pattern, tid0-only fence) ----
    __syncthreads();                         // CTA-scope ordering of all STGs above
    if (tid == 0) {
        __threadfence();                     // cumulative: covers whole CTA's STGs
        s_ticket = atomicAdd(&g_cnt[p], 1);
    }
    __syncthreads();
    if (s_ticket != CHUNKS - 1) return;

    // Last arriver for polygon p: combine 384 (level,point) slots, 64 threads.
    // 6 slots x 8 chunks = 48 independent L2 loads per thread (one quantum).
    if (tid == 0) __threadfence();           // acquire pairing for g_partial reads
    __syncthreads();

    float acc = 0.0f;
    #pragma unroll
    for (int k = 0; k < 6; k++) {
        const int s = k * 64 + tid;          // slot in [0, 384)
        const int l = s >> 7;
        const int n = s & (NN - 1);
        const int idx = l * LVL_STRIDE + p * NN + n;
        float v = __ldcg(&g_partial[0][idx]);
        #pragma unroll
        for (int c = 1; c < CHUNKS; c++)
            v = fminf(v, __ldcg(&g_partial[c][idx]));
        const float w = (l == 0) ? W0 : ((l == 1) ? W1 : W2);
        acc = fmaf(w, sqrtf(fmaxf(v, 0.0f)), acc);
    }
    // deterministic reduce of 64 threads (2 warps)
    #pragma unroll
    for (int off = 16; off > 0; off >>= 1)
        acc += __shfl_xor_sync(0xffffffffu, acc, off);
    if ((tid & 31) == 0) s_w[tid >> 5] = acc;
    __syncthreads();

    if (tid == 0) {
        g_poly[p] = s_w[0] + s_w[1];
        g_cnt[p] = 0;                        // reset for next graph replay
        __threadfence();                     // release g_poly[p] + g_cnt reset
        s_ticket = atomicAdd(&g_cnt2, 1);
    }
    __syncthreads();
    if (s_ticket != PP - 1) return;

    // ---- final: last combiner sums 128 polygon scalars (fixed order) ----
    if (tid == 0) {
        g_cnt2 = 0;                          // reset for next graph replay
        __threadfence();                     // acquire other combiners' g_poly
    }
    __syncthreads();
    float v2 = __ldcg(&g_poly[tid]) + __ldcg(&g_poly[tid + 64]);
    #pragma unroll
    for (int off = 16; off > 0; off >>= 1)
        v2 += __shfl_xor_sync(0xffffffffu, v2, off);
    if ((tid & 31) == 0) s_w[tid >> 5] = v2;
    __syncthreads();
    if (tid == 0) *out = s_w[0] + s_w[1];
}

extern "C" void kernel_launch(void* const* d_in, const int* in_sizes, int n_in,
                              void* d_out, int out_size)
{
    const float* pred0 = (const float*)d_in[0];
    const float* pred1 = (const float*)d_in[1];
    const float* pred2 = (const float*)d_in[2];
    const float* gt    = (const float*)d_in[3];

    dim3 grid(CHUNKS, PP);
    k_all<<<grid, 64>>>(pred0, pred1, pred2, gt, (float*)d_out);
}

// round 17
// speedup vs baseline: 1.3208x; 1.3208x over previous
#include <cuda_runtime.h>

// Problem constants
#define PP      128                 // polygons
#define NN      128                 // pred points per polygon per level
#define MM      1024                // gt points per polygon
#define H       8                   // gt slices per polygon
#define GPH     (MM/H)              // 128 gt per slice
#define NG      (GPH/4)             // 32 groups of 4 gt per slice
#define THREADS 256                 // = 32 point-quads * 8 slices
#define NPART   (3*PP)              // 384 per-(level,polygon) partial sums

// level weights / (3 * P * N)
#define W0 (0.2f/49152.0f)
#define W1 (0.3f/49152.0f)
#define W2 (0.5f/49152.0f)

typedef unsigned long long u64;

// Scratch (no allocations allowed)
__device__ float g_part[NPART];     // per-(level,polygon) unweighted sqrt-sums
__device__ int   g_cnt2;            // ticket (zero-init; winner resets)

// ---- packed f32x2 helpers (sm_103a). fma2 is pure (non-volatile): schedulable. ----
__device__ __forceinline__ u64 pack2(float x) {
    u64 r; asm("mov.b64 %0, {%1, %1};" : "=l"(r) : "f"(x)); return r;
}
__device__ __forceinline__ u64 fma2(u64 a, u64 b, u64 c) {
    u64 d; asm("fma.rn.f32x2 %0, %1, %2, %3;" : "=l"(d) : "l"(a), "l"(b), "l"(c)); return d;
}
__device__ __forceinline__ void min2acc(float& m0, float& m1, u64 t) {
    float2 f = *reinterpret_cast<float2*>(&t);
    m0 = fminf(m0, f.x);
    m1 = fminf(m1, f.y);
}

// 4 points x 4 gt on one (av,bv,cv) group
#define COMPUTE_GROUP(av, bv, cv)                                          \
    do {                                                                   \
        min2acc(m00, m01, fma2(Y0, (bv).x, fma2(X0, (av).x, (cv).x)));     \
        min2acc(m00, m01, fma2(Y0, (bv).y, fma2(X0, (av).y, (cv).y)));     \
        min2acc(m10, m11, fma2(Y1, (bv).x, fma2(X1, (av).x, (cv).x)));     \
        min2acc(m10, m11, fma2(Y1, (bv).y, fma2(X1, (av).y, (cv).y)));     \
        min2acc(m20, m21, fma2(Y2, (bv).x, fma2(X2, (av).x, (cv).x)));     \
        min2acc(m20, m21, fma2(Y2, (bv).y, fma2(X2, (av).y, (cv).y)));     \
        min2acc(m30, m31, fma2(Y3, (bv).x, fma2(X3, (av).x, (cv).x)));     \
        min2acc(m30, m31, fma2(Y3, (bv).y, fma2(X3, (av).y, (cv).y)));     \
    } while (0)

// Single kernel: CTA = (polygon, level). 256 threads = 32 quads x 8 slices.
__global__ __launch_bounds__(THREADS) void k_all(
    const float* __restrict__ pred0, const float* __restrict__ pred1,
    const float* __restrict__ pred2, const float* __restrict__ gt,
    float* __restrict__ out)
{
    __shared__ __align__(16) float sA[MM];
    __shared__ __align__(16) float sB[MM];
    __shared__ __align__(16) float sC[MM];
    __shared__ float s_half[H * NN];       // [slice][point]
    __shared__ float s_warp[8];
    __shared__ int   s_final;

    const int p = blockIdx.x;              // polygon
    const int l = blockIdx.y;              // level
    const int t = threadIdx.x;

    const float* __restrict__ pred = (l == 0) ? pred0 : ((l == 1) ? pred1 : pred2);

    const int q = t & 31;                  // point-quad: points 4q..4q+3
    const int h = t >> 5;                  // gt slice 0..7
    const int n0 = 4 * q;

    // prologue: this thread's 4 points (coords are [...,1:] of last dim 3)
    const int ba = (p * NN + n0) * 3;
    const float x0 = pred[ba + 1],  y0 = pred[ba + 2];
    const float x1 = pred[ba + 4],  y1 = pred[ba + 5];
    const float x2 = pred[ba + 7],  y2 = pred[ba + 8];
    const float x3 = pred[ba + 10], y3 = pred[ba + 11];

    // ---- load ALL gt of this polygon; precompute A=-2gx, B=-2gy, C=|g|^2 ----
    {
        const float2* gsrc = (const float2*)(gt + (size_t)p * MM * 2);
        #pragma unroll
        for (int k = 0; k < 4; k++) {
            int m = t + k * THREADS;
            float2 g = gsrc[m];
            sA[m] = -2.0f * g.x;
            sB[m] = -2.0f * g.y;
            sC[m] = fmaf(g.x, g.x, g.y * g.y);
        }
    }
    __syncthreads();

    const u64 X0 = pack2(x0), Y0 = pack2(y0);
    const u64 X1 = pack2(x1), Y1 = pack2(y1);
    const u64 X2 = pack2(x2), Y2 = pack2(y2);
    const u64 X3 = pack2(x3), Y3 = pack2(y3);

    const float INF = __int_as_float(0x7f800000);
    float m00 = INF, m01 = INF, m10 = INF, m11 = INF;
    float m20 = INF, m21 = INF, m30 = INF, m31 = INF;

    const ulonglong2* A2 = (const ulonglong2*)(sA + h * GPH);
    const ulonglong2* B2 = (const ulonglong2*)(sB + h * GPH);
    const ulonglong2* C2 = (const ulonglong2*)(sC + h * GPH);

    // linear 2-stage pipeline (R15's best-measured loop form)
    ulonglong2 av = A2[0], bv = B2[0], cv = C2[0];
    #pragma unroll 4
    for (int i = 0; i < NG - 1; i++) {
        ulonglong2 an = A2[i + 1], bn = B2[i + 1], cn = C2[i + 1];
        COMPUTE_GROUP(av, bv, cv);
        av = an; bv = bn; cv = cn;
    }
    COMPUTE_GROUP(av, bv, cv);

    // per-(slice, point) partial min d^2
    s_half[h * NN + n0 + 0] = fminf(m00, m01) + fmaf(x0, x0, y0 * y0);
    s_half[h * NN + n0 + 1] = fminf(m10, m11) + fmaf(x1, x1, y1 * y1);
    s_half[h * NN + n0 + 2] = fminf(m20, m21) + fmaf(x2, x2, y2 * y2);
    s_half[h * NN + n0 + 3] = fminf(m30, m31) + fmaf(x3, x3, y3 * y3);
    __syncthreads();

    // ---- combine slices: threads 0..127 own point n = t ----
    float val = 0.0f;
    if (t < NN) {
        const float* sh = s_half + t;
        float v = fminf(fminf(fminf(sh[0 * NN], sh[1 * NN]),
                              fminf(sh[2 * NN], sh[3 * NN])),
                        fminf(fminf(sh[4 * NN], sh[5 * NN]),
                              fminf(sh[6 * NN], sh[7 * NN])));
        val = sqrtf(fmaxf(v, 0.0f));       // unweighted; weight applied at final
    }
    // deterministic fixed-tree reduction (8 warps)
    #pragma unroll
    for (int off = 16; off > 0; off >>= 1)
        val += __shfl_xor_sync(0xffffffffu, val, off);
    if ((t & 31) == 0) s_warp[t >> 5] = val;
    __syncthreads();

    if (t == 0) {
        float s = 0.0f;
        #pragma unroll
        for (int i = 0; i < 4; i++) s += s_warp[i];   // warps >=4 contribute 0
        g_part[l * PP + p] = s;
        __threadfence();                   // release (tid0-only; 384 total)
        int tk = atomicAdd(&g_cnt2, 1);
        s_final = (tk == NPART - 1);
        if (s_final) g_cnt2 = 0;           // reset for next graph replay
    }
    __syncthreads();
    if (!s_final) return;                  // uniform across CTA

    // ---- last CTA: weighted sum of 384 partials (fixed order) ----
    if (t == 0) __threadfence();           // acquire other CTAs' g_part writes
    __syncthreads();

    // idx t in [0,256): levels 0,1; idx t+256 in [256,384): level 2 (t<128)
    const float wA = (t < PP) ? W0 : W1;
    float v2 = wA * __ldcg(&g_part[t]);
    if (t < PP) v2 += W2 * __ldcg(&g_part[t + 256]);
    #pragma unroll
    for (int off = 16; off > 0; off >>= 1)
        v2 += __shfl_xor_sync(0xffffffffu, v2, off);
    if ((t & 31) == 0) s_warp[t >> 5] = v2;
    __syncthreads();
    if (t == 0) {
        float s = 0.0f;
        #pragma unroll
        for (int i = 0; i < 8; i++) s += s_warp[i];
        *out = s;
    }
}

extern "C" void kernel_launch(void* const* d_in, const int* in_sizes, int n_in,
                              void* d_out, int out_size)
{
    const float* pred0 = (const float*)d_in[0];
    const float* pred1 = (const float*)d_in[1];
    const float* pred2 = (const float*)d_in[2];
    const float* gt    = (const float*)d_in[3];

    dim3 grid(PP, 3);
    k_all<<<grid, THREADS>>>(pred0, pred1, pred2, gt, (float*)d_out);
}